// round 15
// baseline (speedup 1.0000x reference)
#include <cuda_runtime.h>
#include <cuda_bf16.h>
#include <cstdint>
#include <cstddef>

// ---------------- problem constants ----------------
#define BATCH 4
#define CDIM  256
#define NPIX  4096   // 64*64
#define KSPLIT 768   // 3 * CDIM : split-bf16 concatenated-K width

// ---------------- device scratch (static; allocation-free) ----------------
// Split layouts (hi/lo bf16 pairs packed along K):
//   Xs row: [Xh | Xl | Xh]   (pairs with Ws row [Wh | Wh | Wl])
//   Qs row: [Qh | Qh | Ql]   (pairs with Ks row [Kh | Kl | Kh])
__device__ __align__(1024) __nv_bfloat16 g_Xs[(size_t)BATCH * NPIX * KSPLIT];  // [b][n][768]
__device__ __align__(1024) __nv_bfloat16 g_Ws[3 * CDIM * KSPLIT];              // [m][o][768]
__device__ __align__(1024) __nv_bfloat16 g_Qs[(size_t)BATCH * NPIX * KSPLIT];  // [b][n][768]
__device__ __align__(1024) __nv_bfloat16 g_Ks[(size_t)BATCH * NPIX * KSPLIT];  // [b][n][768]
__device__ __align__(1024) __nv_bfloat16 g_Vt[(size_t)BATCH * CDIM * NPIX];    // [b][c][n]
__device__ __align__(1024) float         g_E [(size_t)BATCH * NPIX * NPIX];    // energy fp32
__device__ __align__(1024) __nv_bfloat16 g_At[(size_t)BATCH * NPIX * NPIX];    // attn bf16
__device__ __align__(1024) float         g_O [(size_t)BATCH * NPIX * CDIM];    // O^T [b][n][c]

// ---------------- small helpers ----------------
static __device__ __forceinline__ uint32_t smem_u32(const void* p) {
    uint32_t a;
    asm("{ .reg .u64 t; cvta.to.shared.u64 t, %1; cvt.u32.u64 %0, t; }" : "=r"(a) : "l"(p));
    return a;
}
#define CP_ASYNC16(dst, src) \
    asm volatile("cp.async.cg.shared.global [%0], [%1], 16;" :: "r"(dst), "l"(src) : "memory")
#define CP_COMMIT()  asm volatile("cp.async.commit_group;" ::: "memory")
#define CP_WAIT0()   asm volatile("cp.async.wait_group 0;" ::: "memory")
#define CP_WAIT1()   asm volatile("cp.async.wait_group 1;" ::: "memory")

// smem tile geometry: rows x 40 bf16 (32 data + 8 pad) = 80 B/row
#define ROW_B       80u
#define A_TILE_B    (128u * ROW_B)          // 10240

// =====================================================================
// GEMM: D[M,N] = A[M,K] @ B[N,K]^T  (+ optional per-row / per-col bias)
// A, B bf16 row-major (K contiguous). CTA tile 128 x NT x 32, 256 threads,
// 8 warps in 2x4 (each warp 64 x NT/4). 3-stage cp.async pipeline,
// ldmatrix fragment loads, single __syncthreads per k-tile.
// MODE 0: store OutT (float or bf16) at D[r*ldd + col]
// MODE 1: split-write Q rows [hi | hi | lo] into bf16 D, ldd = 768
// MODE 2: split-write K rows [hi | lo | hi] into bf16 D, ldd = 768
// MODE 3: fused QK: cols [0,256) -> Q-split into D (bias biasCol),
//                   cols [256,512) -> K-split into D2 (bias biasCol2)
// =====================================================================
template <typename OutT, int MODE, int NT>
__global__ void __launch_bounds__(256, (NT == 128) ? 2 : 1)
gemm_kernel(const __nv_bfloat16* __restrict__ A, int lda, size_t strideA,
            const __nv_bfloat16* __restrict__ B, int ldb, size_t strideB,
            OutT* __restrict__ D, int ldd, size_t strideD,
            int K,
            const float* __restrict__ biasRow,
            const float* __restrict__ biasCol,
            OutT* __restrict__ D2,
            const float* __restrict__ biasCol2)
{
    constexpr int NSPAN = NT / 4;          // warp n-span: 32 or 64
    constexpr int NB    = NSPAN / 16;      // B ldmatrix.x4 per k-slice: 2 or 4
    constexpr int NI    = NSPAN / 8;       // mma n-count: 4 or 8
    constexpr uint32_t B_TILE_B  = (uint32_t)NT * ROW_B;
    constexpr uint32_t STAGE_B   = A_TILE_B + B_TILE_B;

    extern __shared__ __align__(128) char dynsm[];
    const uint32_t smBase = smem_u32(dynsm);

    const int m0 = blockIdx.x * 128;
    const int n0 = blockIdx.y * NT;
    A += (size_t)blockIdx.z * strideA;
    B += (size_t)blockIdx.z * strideB;
    D += (size_t)blockIdx.z * strideD;

    const int tid  = threadIdx.x;
    const int lane = tid & 31;
    const int wid  = tid >> 5;
    const int wm   = (wid >> 2) * 64;       // warp M offset in tile
    const int wn   = (wid & 3) * NSPAN;     // warp N offset in tile
    const int g    = lane >> 2;             // groupID
    const int tig  = lane & 3;              // threadID in group

    // ldmatrix per-lane byte offsets within a tile
    //  A (x4): matrices {rows0-7,klo},{rows8-15,klo},{rows0-7,khi},{rows8-15,khi}
    const uint32_t aOff = (uint32_t)(wm + (lane & 15)) * ROW_B + (uint32_t)((lane >> 4) * 16);
    //  B (x4): matrices {n0-7,klo},{n0-7,khi},{n8-15,klo},{n8-15,khi}
    const uint32_t bOff = (uint32_t)(wn + ((lane >> 4) << 3) + (lane & 7)) * ROW_B
                        + (uint32_t)(((lane >> 3) & 1) * 16);

    float acc[4][NI][4];
#pragma unroll
    for (int i = 0; i < 4; i++)
#pragma unroll
        for (int j = 0; j < NI; j++)
#pragma unroll
            for (int r = 0; r < 4; r++) acc[i][j][r] = 0.f;

    const int nk = K >> 5;

    // ---- async tile loader: A 512 uint4, B NT*4 uint4 per stage ----
    auto issue = [&](int s, int k0) {
        uint32_t baseA = smBase + (uint32_t)s * STAGE_B;
        uint32_t baseB = baseA + A_TILE_B;
#pragma unroll
        for (int h = 0; h < 2; h++) {
            int i   = tid + h * 256;
            int row = i >> 2, c16 = i & 3;
            uint32_t off = (uint32_t)row * ROW_B + (uint32_t)c16 * 16u;
            CP_ASYNC16(baseA + off, (const void*)(A + (size_t)(m0 + row) * lda + k0 + c16 * 8));
        }
#pragma unroll
        for (int h = 0; h < NT / 64; h++) {
            int i   = tid + h * 256;
            int row = i >> 2, c16 = i & 3;
            uint32_t off = (uint32_t)row * ROW_B + (uint32_t)c16 * 16u;
            CP_ASYNC16(baseB + off, (const void*)(B + (size_t)(n0 + row) * ldb + k0 + c16 * 8));
        }
        CP_COMMIT();
    };

    auto compute = [&](uint32_t aBase) {
        const uint32_t bBase = aBase + A_TILE_B;
#pragma unroll
        for (int ks = 0; ks < 2; ks++) {
            const uint32_t koff = (uint32_t)ks * 32u;   // 16 bf16 = 32 bytes
            uint32_t b[NB][4];
#pragma unroll
            for (int p = 0; p < NB; p++) {
                uint32_t addr = bBase + bOff + (uint32_t)p * (16u * ROW_B) + koff;
                asm volatile(
                    "ldmatrix.sync.aligned.m8n8.x4.shared.b16 {%0,%1,%2,%3}, [%4];"
                    : "=r"(b[p][0]), "=r"(b[p][1]), "=r"(b[p][2]), "=r"(b[p][3])
                    : "r"(addr));
            }
#pragma unroll
            for (int mi = 0; mi < 4; mi++) {
                uint32_t a0, a1, a2, a3;
                uint32_t addr = aBase + aOff + (uint32_t)mi * (16u * ROW_B) + koff;
                asm volatile(
                    "ldmatrix.sync.aligned.m8n8.x4.shared.b16 {%0,%1,%2,%3}, [%4];"
                    : "=r"(a0), "=r"(a1), "=r"(a2), "=r"(a3)
                    : "r"(addr));
#pragma unroll
                for (int ni = 0; ni < NI; ni++) {
                    const uint32_t b0 = b[ni >> 1][(ni & 1) * 2 + 0];
                    const uint32_t b1 = b[ni >> 1][(ni & 1) * 2 + 1];
                    asm volatile(
                        "mma.sync.aligned.m16n8k16.row.col.f32.bf16.bf16.f32 "
                        "{%0,%1,%2,%3}, {%4,%5,%6,%7}, {%8,%9}, {%0,%1,%2,%3};"
                        : "+f"(acc[mi][ni][0]), "+f"(acc[mi][ni][1]),
                          "+f"(acc[mi][ni][2]), "+f"(acc[mi][ni][3])
                        : "r"(a0), "r"(a1), "r"(a2), "r"(a3),
                          "r"(b0), "r"(b1));
                }
            }
        }
    };

    // ---- 3-stage pipeline, one barrier per k-tile ----
    issue(0, 0);
    issue(1, 32);
    for (int kt = 0; kt < nk; kt++) {
        if (kt == nk - 1) { CP_WAIT0(); }   // last group must be fully complete
        else             { CP_WAIT1(); }    // group kt complete, kt+1 may pend
        __syncthreads();                    // tile kt visible; stage (kt+2)%3 free
        if (kt + 2 < nk) issue((kt + 2) % 3, (kt + 2) * 32);
        compute(smBase + (uint32_t)(kt % 3) * STAGE_B);
    }

    // ---- epilogue ----
#pragma unroll
    for (int mi = 0; mi < 4; mi++) {
#pragma unroll
        for (int ni = 0; ni < NI; ni++) {
            int row  = m0 + wm + mi * 16 + g;
            int colg = n0 + wn + ni * 8 + tig * 2;
#pragma unroll
            for (int p = 0; p < 2; p++) {
                int r = row + p * 8;
                float v0 = acc[mi][ni][2 * p + 0];
                float v1 = acc[mi][ni][2 * p + 1];
                if constexpr (MODE == 0) {
                    if (biasRow) { float br = biasRow[r]; v0 += br; v1 += br; }
                    if (biasCol) { v0 += biasCol[colg]; v1 += biasCol[colg + 1]; }
                    if constexpr (sizeof(OutT) == 4) {
                        float2 f2 = make_float2(v0, v1);
                        *(float2*)((float*)D + (size_t)r * ldd + colg) = f2;
                    } else {
                        __nv_bfloat162 h = __floats2bfloat162_rn(v0, v1);
                        *(__nv_bfloat162*)((__nv_bfloat16*)D + (size_t)r * ldd + colg) = h;
                    }
                } else {
                    // split-bf16 writes (Q/K layouts)
                    bool isQ;
                    int col;
                    __nv_bfloat16* base;
                    if constexpr (MODE == 1) {
                        isQ = true;  col = colg;
                        v0 += biasCol[col]; v1 += biasCol[col + 1];
                        base = (__nv_bfloat16*)D + (size_t)r * ldd + col;
                    } else if constexpr (MODE == 2) {
                        isQ = false; col = colg;
                        v0 += biasCol[col]; v1 += biasCol[col + 1];
                        base = (__nv_bfloat16*)D + (size_t)r * ldd + col;
                    } else {           // MODE 3: fused QK
                        isQ = (colg < 256);
                        col = isQ ? colg : colg - 256;
                        const float* bc = isQ ? biasCol : biasCol2;
                        v0 += bc[col]; v1 += bc[col + 1];
                        base = (__nv_bfloat16*)(isQ ? D : D2) + (size_t)r * ldd + col;
                    }
                    __nv_bfloat16 h0 = __float2bfloat16(v0);
                    __nv_bfloat16 h1 = __float2bfloat16(v1);
                    __nv_bfloat16 l0 = __float2bfloat16(v0 - __bfloat162float(h0));
                    __nv_bfloat16 l1 = __float2bfloat16(v1 - __bfloat162float(h1));
                    __nv_bfloat162 hh; hh.x = h0; hh.y = h1;
                    __nv_bfloat162 ll; ll.x = l0; ll.y = l1;
                    if (isQ) {                         // Q: [hi | hi | lo]
                        *(__nv_bfloat162*)(base)       = hh;
                        *(__nv_bfloat162*)(base + 256) = hh;
                        *(__nv_bfloat162*)(base + 512) = ll;
                    } else {                           // K: [hi | lo | hi]
                        *(__nv_bfloat162*)(base)       = hh;
                        *(__nv_bfloat162*)(base + 256) = ll;
                        *(__nv_bfloat162*)(base + 512) = hh;
                    }
                }
            }
        }
    }
}

#define SMEM_128  (3u * (A_TILE_B + 128u * ROW_B))   // 61440
#define SMEM_256  (3u * (A_TILE_B + 256u * ROW_B))   // 92160

// =====================================================================
// x[b][c][n] fp32 -> Xs[b][n][768] split bf16 rows [Xh | Xl | Xh]
// =====================================================================
__global__ void transpose_x_kernel(const float* __restrict__ x, __nv_bfloat16* __restrict__ xs)
{
    __shared__ float tile[32][33];
    const int b  = blockIdx.z;
    const int n0 = blockIdx.x * 32;
    const int c0 = blockIdx.y * 32;
    const int tx = threadIdx.x, ty = threadIdx.y;
    const float* xb = x + ((size_t)b * CDIM + c0) * NPIX + n0;
#pragma unroll
    for (int j = 0; j < 4; j++)
        tile[ty + 8 * j][tx] = xb[(size_t)(ty + 8 * j) * NPIX + tx];
    __syncthreads();
    __nv_bfloat16* xo = xs + ((size_t)b * NPIX + n0) * KSPLIT + c0;
#pragma unroll
    for (int j = 0; j < 4; j++) {
        float f = tile[tx][ty + 8 * j];
        __nv_bfloat16 hi = __float2bfloat16(f);
        __nv_bfloat16 lo = __float2bfloat16(f - __bfloat162float(hi));
        __nv_bfloat16* row = xo + (size_t)(ty + 8 * j) * KSPLIT;
        row[tx]       = hi;
        row[tx + 256] = lo;
        row[tx + 512] = hi;
    }
}

// =====================================================================
// W fp32 -> Ws[m][o][768] split rows [Wh | Wh | Wl]
// =====================================================================
__global__ void convert_w_kernel(const float* __restrict__ wq,
                                 const float* __restrict__ wk,
                                 const float* __restrict__ wv,
                                 __nv_bfloat16* __restrict__ dst)
{
    const int m = blockIdx.y;
    const float* s = (m == 0) ? wq : (m == 1) ? wk : wv;
    int i = blockIdx.x * 256 + threadIdx.x;   // 65536 elements
    int o = i >> 8, c = i & 255;
    float f = s[i];
    __nv_bfloat16 hi = __float2bfloat16(f);
    __nv_bfloat16 lo = __float2bfloat16(f - __bfloat162float(hi));
    __nv_bfloat16* row = dst + ((size_t)m * CDIM + o) * KSPLIT;
    row[c]       = hi;
    row[c + 256] = hi;
    row[c + 512] = lo;
}

// =====================================================================
// Row softmax: E fp32 [16384][4096] -> attn bf16, one CTA per row,
// entire row register-resident (16 floats/thread), single gmem pass.
// =====================================================================
__global__ void __launch_bounds__(256)
softmax_kernel(const float* __restrict__ E, __nv_bfloat16* __restrict__ Aout)
{
    const size_t row = blockIdx.x;
    const float4* e = (const float4*)(E + row * NPIX);
    const int t = threadIdx.x;
    const int lane = t & 31, warp = t >> 5;
    __shared__ float red[8];

    float4 v[4];
    float mx = -3.0e38f;
#pragma unroll
    for (int i = 0; i < 4; i++) {
        v[i] = e[t + i * 256];
        mx = fmaxf(mx, fmaxf(fmaxf(v[i].x, v[i].y), fmaxf(v[i].z, v[i].w)));
    }
#pragma unroll
    for (int o = 16; o > 0; o >>= 1) mx = fmaxf(mx, __shfl_xor_sync(0xffffffffu, mx, o));
    if (lane == 0) red[warp] = mx;
    __syncthreads();
    float rmax = red[0];
#pragma unroll
    for (int i = 1; i < 8; i++) rmax = fmaxf(rmax, red[i]);
    __syncthreads();

    float s = 0.f;
#pragma unroll
    for (int i = 0; i < 4; i++) {
        v[i].x = __expf(v[i].x - rmax);
        v[i].y = __expf(v[i].y - rmax);
        v[i].z = __expf(v[i].z - rmax);
        v[i].w = __expf(v[i].w - rmax);
        s += (v[i].x + v[i].y) + (v[i].z + v[i].w);
    }
#pragma unroll
    for (int o = 16; o > 0; o >>= 1) s += __shfl_xor_sync(0xffffffffu, s, o);
    if (lane == 0) red[warp] = s;
    __syncthreads();
    float rsum = 0.f;
#pragma unroll
    for (int i = 0; i < 8; i++) rsum += red[i];
    const float inv = 1.0f / rsum;

    uint2* a = (uint2*)(Aout + row * NPIX);
#pragma unroll
    for (int i = 0; i < 4; i++) {
        __nv_bfloat162 lo = __floats2bfloat162_rn(v[i].x * inv, v[i].y * inv);
        __nv_bfloat162 hi = __floats2bfloat162_rn(v[i].z * inv, v[i].w * inv);
        uint2 pk;
        pk.x = *(uint32_t*)&lo;
        pk.y = *(uint32_t*)&hi;
        a[t + i * 256] = pk;
    }
}

// =====================================================================
// out[b][c][n] = gamma * O^T[b][n][c] + x[b][c][n]   (32x32 transpose)
// =====================================================================
__global__ void final_kernel(const float* __restrict__ O, const float* __restrict__ x,
                             const float* __restrict__ gamma, float* __restrict__ out)
{
    __shared__ float tile[32][33];
    const int b  = blockIdx.z;
    const int n0 = blockIdx.x * 32;
    const int c0 = blockIdx.y * 32;
    const int tx = threadIdx.x, ty = threadIdx.y;
    const float gm = gamma[0];
    const float* Ob = O + ((size_t)b * NPIX + n0) * CDIM + c0;
#pragma unroll
    for (int j = 0; j < 4; j++)
        tile[ty + 8 * j][tx] = Ob[(size_t)(ty + 8 * j) * CDIM + tx];   // tile[n][c]
    __syncthreads();
#pragma unroll
    for (int j = 0; j < 4; j++) {
        size_t idx = ((size_t)b * CDIM + c0 + ty + 8 * j) * NPIX + n0 + tx;
        out[idx] = gm * tile[tx][ty + 8 * j] + x[idx];
    }
}

// =====================================================================
// launch
// =====================================================================
extern "C" void kernel_launch(void* const* d_in, const int* in_sizes, int n_in,
                              void* d_out, int out_size)
{
    const float* x     = (const float*)d_in[0];
    const float* Wq    = (const float*)d_in[1];
    const float* bq    = (const float*)d_in[2];
    const float* Wk    = (const float*)d_in[3];
    const float* bk    = (const float*)d_in[4];
    const float* Wv    = (const float*)d_in[5];
    const float* bv    = (const float*)d_in[6];
    const float* gamma = (const float*)d_in[7];
    float* out = (float*)d_out;

    __nv_bfloat16 *Xs, *Ws, *Qs, *Ks, *Vt, *At;
    float *E, *O;
    cudaGetSymbolAddress((void**)&Xs, g_Xs);
    cudaGetSymbolAddress((void**)&Ws, g_Ws);
    cudaGetSymbolAddress((void**)&Qs, g_Qs);
    cudaGetSymbolAddress((void**)&Ks, g_Ks);
    cudaGetSymbolAddress((void**)&Vt, g_Vt);
    cudaGetSymbolAddress((void**)&At, g_At);
    cudaGetSymbolAddress((void**)&E,  g_E);
    cudaGetSymbolAddress((void**)&O,  g_O);

    // opt-in dynamic smem
    cudaFuncSetAttribute(gemm_kernel<__nv_bfloat16, 3, 128>,
                         cudaFuncAttributeMaxDynamicSharedMemorySize, SMEM_128);
    cudaFuncSetAttribute(gemm_kernel<__nv_bfloat16, 0, 128>,
                         cudaFuncAttributeMaxDynamicSharedMemorySize, SMEM_128);
    cudaFuncSetAttribute(gemm_kernel<float, 0, 128>,
                         cudaFuncAttributeMaxDynamicSharedMemorySize, SMEM_128);
    cudaFuncSetAttribute(gemm_kernel<float, 0, 256>,
                         cudaFuncAttributeMaxDynamicSharedMemorySize, SMEM_256);

    // 1) converts into split layouts
    transpose_x_kernel<<<dim3(NPIX / 32, CDIM / 32, BATCH), dim3(32, 8)>>>(x, Xs);
    convert_w_kernel<<<dim3(256, 3), 256>>>(Wq, Wk, Wv, Ws);

    const size_t sNC  = (size_t)NPIX * CDIM;     // 4096*256
    const size_t sNN  = (size_t)NPIX * NPIX;     // 4096*4096
    const size_t s768 = (size_t)NPIX * KSPLIT;   // 4096*768

    // 2) fused QK proj: [Q|K] = Xs @ [Wsq;Wsk]^T : M=16384, N=512, K=768
    //    split outputs routed per-column to Qs (Q layout) / Ks (K layout)
    gemm_kernel<__nv_bfloat16, 3, 128><<<dim3(128, 4, 1), 256, SMEM_128>>>(
        Xs, KSPLIT, 0, Ws, KSPLIT, 0,
        Qs, KSPLIT, 0, KSPLIT, nullptr, bq, Ks, bk);

    // 3) Vt[b] = Wsv @ Xs[b]^T + bv(row) : M=256, N=4096, K=768, per batch
    gemm_kernel<__nv_bfloat16, 0, 128><<<dim3(2, 32, BATCH), 256, SMEM_128>>>(
        Ws + 2 * CDIM * KSPLIT, KSPLIT, 0, Xs, KSPLIT, s768,
        Vt, NPIX, sNC, KSPLIT, bv, nullptr, nullptr, nullptr);

    // 4) E[b] = Qs[b] @ Ks[b]^T : M=N=4096, K=768, fp32 out, 128x256 tile
    //    = Qh.Kh + Qh.Kl + Ql.Kh  (fp32-grade energies)
    gemm_kernel<float, 0, 256><<<dim3(32, 16, BATCH), 256, SMEM_256>>>(
        Qs, KSPLIT, s768, Ks, KSPLIT, s768,
        E, NPIX, sNN, KSPLIT, nullptr, nullptr, nullptr, nullptr);

    // 5) row softmax -> attn bf16
    softmax_kernel<<<BATCH * NPIX, 256>>>(E, At);

    // 6) O^T[b] = attn[b] @ Vt[b]^T : M=4096, N=256, K=4096, fp32 out
    gemm_kernel<float, 0, 128><<<dim3(32, 2, BATCH), 256, SMEM_128>>>(
        At, NPIX, sNN, Vt, NPIX, sNC,
        O, CDIM, sNC, NPIX, nullptr, nullptr, nullptr, nullptr);

    // 7) out = gamma * O^T + x
    final_kernel<<<dim3(NPIX / 32, CDIM / 32, BATCH), dim3(32, 8)>>>(O, x, gamma, out);
}

// round 16
// speedup vs baseline: 1.1425x; 1.1425x over previous
#include <cuda_runtime.h>
#include <cuda_bf16.h>
#include <cuda_fp16.h>
#include <cstdint>
#include <cstddef>

// ---------------- problem constants ----------------
#define BATCH 4
#define CDIM  256
#define NPIX  4096   // 64*64
#define KSPLIT 768   // 3 * CDIM : split-bf16 concatenated-K width

// ---------------- device scratch (static; allocation-free) ----------------
// Split layouts (hi/lo bf16 pairs packed along K):
//   Xs row: [Xh | Xl | Xh]   (pairs with Ws row [Wh | Wh | Wl])
//   Qs row: [Qh | Qh | Ql]   (pairs with Ks row [Kh | Kl | Kh])
__device__ __align__(1024) __nv_bfloat16 g_Xs[(size_t)BATCH * NPIX * KSPLIT];  // [b][n][768]
__device__ __align__(1024) __nv_bfloat16 g_Ws[3 * CDIM * KSPLIT];              // [m][o][768]
__device__ __align__(1024) __nv_bfloat16 g_Qs[(size_t)BATCH * NPIX * KSPLIT];  // [b][n][768]
__device__ __align__(1024) __nv_bfloat16 g_Ks[(size_t)BATCH * NPIX * KSPLIT];  // [b][n][768]
__device__ __align__(1024) __nv_bfloat16 g_Vt[(size_t)BATCH * CDIM * NPIX];    // [b][c][n]
__device__ __align__(1024) __half        g_Eh[(size_t)BATCH * NPIX * NPIX];    // energy fp16
__device__ __align__(1024) __nv_bfloat16 g_At[(size_t)BATCH * NPIX * NPIX];    // attn bf16
__device__ __align__(1024) float         g_O [(size_t)BATCH * NPIX * CDIM];    // O^T [b][n][c]

// ---------------- small helpers ----------------
static __device__ __forceinline__ uint32_t smem_u32(const void* p) {
    uint32_t a;
    asm("{ .reg .u64 t; cvta.to.shared.u64 t, %1; cvt.u32.u64 %0, t; }" : "=r"(a) : "l"(p));
    return a;
}
#define CP_ASYNC16(dst, src) \
    asm volatile("cp.async.cg.shared.global [%0], [%1], 16;" :: "r"(dst), "l"(src) : "memory")
#define CP_COMMIT()  asm volatile("cp.async.commit_group;" ::: "memory")
#define CP_WAIT0()   asm volatile("cp.async.wait_group 0;" ::: "memory")
#define CP_WAIT1()   asm volatile("cp.async.wait_group 1;" ::: "memory")

// pack two fp32 into a 2x16-bit word, type-directed
static __device__ __forceinline__ uint32_t pack2(float v0, float v1, const __nv_bfloat16*) {
    __nv_bfloat162 h = __floats2bfloat162_rn(v0, v1);
    return *(uint32_t*)&h;
}
static __device__ __forceinline__ uint32_t pack2(float v0, float v1, const __half*) {
    __half2 h = __floats2half2_rn(v0, v1);
    return *(uint32_t*)&h;
}

// smem tile geometry: rows x 40 bf16 (32 data + 8 pad) = 80 B/row
#define ROW_B       80u
#define A_TILE_B    (128u * ROW_B)          // 10240
#define SMEM_128    (3u * (A_TILE_B + 128u * ROW_B))   // 61440

// =====================================================================
// GEMM: D[M,N] = A[M,K] @ B[N,K]^T  (+ optional per-row / per-col bias)
// A, B bf16 row-major (K contiguous). CTA tile 128 x NT x 32, 256 threads,
// 8 warps in 2x4 (each warp 64 x NT/4). 3-stage cp.async pipeline,
// ldmatrix fragment loads, single __syncthreads per k-tile.
// MODE 0: store OutT (float / bf16 / half) at D[r*ldd + col]
// MODE 3: fused QK: cols [0,256) -> Q-split [hi|hi|lo] into D (bias biasCol),
//                   cols [256,512) -> K-split [hi|lo|hi] into D2 (bias biasCol2)
// =====================================================================
template <typename OutT, int MODE, int NT>
__global__ void __launch_bounds__(256, (NT == 128) ? 2 : 1)
gemm_kernel(const __nv_bfloat16* __restrict__ A, int lda, size_t strideA,
            const __nv_bfloat16* __restrict__ B, int ldb, size_t strideB,
            OutT* __restrict__ D, int ldd, size_t strideD,
            int K,
            const float* __restrict__ biasRow,
            const float* __restrict__ biasCol,
            OutT* __restrict__ D2,
            const float* __restrict__ biasCol2)
{
    constexpr int NSPAN = NT / 4;          // warp n-span: 32
    constexpr int NB    = NSPAN / 16;      // B ldmatrix.x4 per k-slice
    constexpr int NI    = NSPAN / 8;       // mma n-count
    constexpr uint32_t B_TILE_B  = (uint32_t)NT * ROW_B;
    constexpr uint32_t STAGE_B   = A_TILE_B + B_TILE_B;

    extern __shared__ __align__(128) char dynsm[];
    const uint32_t smBase = smem_u32(dynsm);

    const int m0 = blockIdx.x * 128;
    const int n0 = blockIdx.y * NT;
    A += (size_t)blockIdx.z * strideA;
    B += (size_t)blockIdx.z * strideB;
    D += (size_t)blockIdx.z * strideD;

    const int tid  = threadIdx.x;
    const int lane = tid & 31;
    const int wid  = tid >> 5;
    const int wm   = (wid >> 2) * 64;       // warp M offset in tile
    const int wn   = (wid & 3) * NSPAN;     // warp N offset in tile
    const int g    = lane >> 2;             // groupID
    const int tig  = lane & 3;              // threadID in group

    // ldmatrix per-lane byte offsets within a tile
    //  A (x4): matrices {rows0-7,klo},{rows8-15,klo},{rows0-7,khi},{rows8-15,khi}
    const uint32_t aOff = (uint32_t)(wm + (lane & 15)) * ROW_B + (uint32_t)((lane >> 4) * 16);
    //  B (x4): matrices {n0-7,klo},{n0-7,khi},{n8-15,klo},{n8-15,khi}
    const uint32_t bOff = (uint32_t)(wn + ((lane >> 4) << 3) + (lane & 7)) * ROW_B
                        + (uint32_t)(((lane >> 3) & 1) * 16);

    float acc[4][NI][4];
#pragma unroll
    for (int i = 0; i < 4; i++)
#pragma unroll
        for (int j = 0; j < NI; j++)
#pragma unroll
            for (int r = 0; r < 4; r++) acc[i][j][r] = 0.f;

    const int nk = K >> 5;

    // ---- async tile loader: A 512 uint4, B NT*4 uint4 per stage ----
    auto issue = [&](int s, int k0) {
        uint32_t baseA = smBase + (uint32_t)s * STAGE_B;
        uint32_t baseB = baseA + A_TILE_B;
#pragma unroll
        for (int h = 0; h < 2; h++) {
            int i   = tid + h * 256;
            int row = i >> 2, c16 = i & 3;
            uint32_t off = (uint32_t)row * ROW_B + (uint32_t)c16 * 16u;
            CP_ASYNC16(baseA + off, (const void*)(A + (size_t)(m0 + row) * lda + k0 + c16 * 8));
        }
#pragma unroll
        for (int h = 0; h < NT / 64; h++) {
            int i   = tid + h * 256;
            int row = i >> 2, c16 = i & 3;
            uint32_t off = (uint32_t)row * ROW_B + (uint32_t)c16 * 16u;
            CP_ASYNC16(baseB + off, (const void*)(B + (size_t)(n0 + row) * ldb + k0 + c16 * 8));
        }
        CP_COMMIT();
    };

    auto compute = [&](uint32_t aBase) {
        const uint32_t bBase = aBase + A_TILE_B;
#pragma unroll
        for (int ks = 0; ks < 2; ks++) {
            const uint32_t koff = (uint32_t)ks * 32u;   // 16 bf16 = 32 bytes
            uint32_t b[NB][4];
#pragma unroll
            for (int p = 0; p < NB; p++) {
                uint32_t addr = bBase + bOff + (uint32_t)p * (16u * ROW_B) + koff;
                asm volatile(
                    "ldmatrix.sync.aligned.m8n8.x4.shared.b16 {%0,%1,%2,%3}, [%4];"
                    : "=r"(b[p][0]), "=r"(b[p][1]), "=r"(b[p][2]), "=r"(b[p][3])
                    : "r"(addr));
            }
#pragma unroll
            for (int mi = 0; mi < 4; mi++) {
                uint32_t a0, a1, a2, a3;
                uint32_t addr = aBase + aOff + (uint32_t)mi * (16u * ROW_B) + koff;
                asm volatile(
                    "ldmatrix.sync.aligned.m8n8.x4.shared.b16 {%0,%1,%2,%3}, [%4];"
                    : "=r"(a0), "=r"(a1), "=r"(a2), "=r"(a3)
                    : "r"(addr));
#pragma unroll
                for (int ni = 0; ni < NI; ni++) {
                    const uint32_t b0 = b[ni >> 1][(ni & 1) * 2 + 0];
                    const uint32_t b1 = b[ni >> 1][(ni & 1) * 2 + 1];
                    asm volatile(
                        "mma.sync.aligned.m16n8k16.row.col.f32.bf16.bf16.f32 "
                        "{%0,%1,%2,%3}, {%4,%5,%6,%7}, {%8,%9}, {%0,%1,%2,%3};"
                        : "+f"(acc[mi][ni][0]), "+f"(acc[mi][ni][1]),
                          "+f"(acc[mi][ni][2]), "+f"(acc[mi][ni][3])
                        : "r"(a0), "r"(a1), "r"(a2), "r"(a3),
                          "r"(b0), "r"(b1));
                }
            }
        }
    };

    // ---- 3-stage pipeline, one barrier per k-tile ----
    issue(0, 0);
    issue(1, 32);
    for (int kt = 0; kt < nk; kt++) {
        if (kt == nk - 1) { CP_WAIT0(); }   // last group must be fully complete
        else             { CP_WAIT1(); }    // group kt complete, kt+1 may pend
        __syncthreads();                    // tile kt visible; stage (kt+2)%3 free
        if (kt + 2 < nk) issue((kt + 2) % 3, (kt + 2) * 32);
        compute(smBase + (uint32_t)(kt % 3) * STAGE_B);
    }

    // ---- epilogue ----
#pragma unroll
    for (int mi = 0; mi < 4; mi++) {
#pragma unroll
        for (int ni = 0; ni < NI; ni++) {
            int row  = m0 + wm + mi * 16 + g;
            int colg = n0 + wn + ni * 8 + tig * 2;
#pragma unroll
            for (int p = 0; p < 2; p++) {
                int r = row + p * 8;
                float v0 = acc[mi][ni][2 * p + 0];
                float v1 = acc[mi][ni][2 * p + 1];
                if constexpr (MODE == 0) {
                    if (biasRow) { float br = biasRow[r]; v0 += br; v1 += br; }
                    if (biasCol) { v0 += biasCol[colg]; v1 += biasCol[colg + 1]; }
                    if constexpr (sizeof(OutT) == 4) {
                        float2 f2 = make_float2(v0, v1);
                        *(float2*)((float*)D + (size_t)r * ldd + colg) = f2;
                    } else {
                        uint32_t pk = pack2(v0, v1, (const OutT*)nullptr);
                        *(uint32_t*)((OutT*)D + (size_t)r * ldd + colg) = pk;
                    }
                } else {
                    // MODE 3: fused QK split-bf16 writes
                    const bool isQ = (colg < 256);
                    const int  col = isQ ? colg : colg - 256;
                    const float* bc = isQ ? biasCol : biasCol2;
                    v0 += bc[col]; v1 += bc[col + 1];
                    __nv_bfloat16* base =
                        (__nv_bfloat16*)(isQ ? (void*)D : (void*)D2) + (size_t)r * ldd + col;
                    __nv_bfloat16 h0 = __float2bfloat16(v0);
                    __nv_bfloat16 h1 = __float2bfloat16(v1);
                    __nv_bfloat16 l0 = __float2bfloat16(v0 - __bfloat162float(h0));
                    __nv_bfloat16 l1 = __float2bfloat16(v1 - __bfloat162float(h1));
                    __nv_bfloat162 hh; hh.x = h0; hh.y = h1;
                    __nv_bfloat162 ll; ll.x = l0; ll.y = l1;
                    if (isQ) {                         // Q: [hi | hi | lo]
                        *(__nv_bfloat162*)(base)       = hh;
                        *(__nv_bfloat162*)(base + 256) = hh;
                        *(__nv_bfloat162*)(base + 512) = ll;
                    } else {                           // K: [hi | lo | hi]
                        *(__nv_bfloat162*)(base)       = hh;
                        *(__nv_bfloat162*)(base + 256) = ll;
                        *(__nv_bfloat162*)(base + 512) = hh;
                    }
                }
            }
        }
    }
}

// =====================================================================
// x[b][c][n] fp32 -> Xs[b][n][768] split bf16 rows [Xh | Xl | Xh]
// =====================================================================
__global__ void transpose_x_kernel(const float* __restrict__ x, __nv_bfloat16* __restrict__ xs)
{
    __shared__ float tile[32][33];
    const int b  = blockIdx.z;
    const int n0 = blockIdx.x * 32;
    const int c0 = blockIdx.y * 32;
    const int tx = threadIdx.x, ty = threadIdx.y;
    const float* xb = x + ((size_t)b * CDIM + c0) * NPIX + n0;
#pragma unroll
    for (int j = 0; j < 4; j++)
        tile[ty + 8 * j][tx] = xb[(size_t)(ty + 8 * j) * NPIX + tx];
    __syncthreads();
    __nv_bfloat16* xo = xs + ((size_t)b * NPIX + n0) * KSPLIT + c0;
#pragma unroll
    for (int j = 0; j < 4; j++) {
        float f = tile[tx][ty + 8 * j];
        __nv_bfloat16 hi = __float2bfloat16(f);
        __nv_bfloat16 lo = __float2bfloat16(f - __bfloat162float(hi));
        __nv_bfloat16* row = xo + (size_t)(ty + 8 * j) * KSPLIT;
        row[tx]       = hi;
        row[tx + 256] = lo;
        row[tx + 512] = hi;
    }
}

// =====================================================================
// W fp32 -> Ws[m][o][768] split rows [Wh | Wh | Wl]
// =====================================================================
__global__ void convert_w_kernel(const float* __restrict__ wq,
                                 const float* __restrict__ wk,
                                 const float* __restrict__ wv,
                                 __nv_bfloat16* __restrict__ dst)
{
    const int m = blockIdx.y;
    const float* s = (m == 0) ? wq : (m == 1) ? wk : wv;
    int i = blockIdx.x * 256 + threadIdx.x;   // 65536 elements
    int o = i >> 8, c = i & 255;
    float f = s[i];
    __nv_bfloat16 hi = __float2bfloat16(f);
    __nv_bfloat16 lo = __float2bfloat16(f - __bfloat162float(hi));
    __nv_bfloat16* row = dst + ((size_t)m * CDIM + o) * KSPLIT;
    row[c]       = hi;
    row[c + 256] = hi;
    row[c + 512] = lo;
}

// =====================================================================
// Row softmax: E fp16 [16384][4096] -> attn bf16, one CTA per row,
// entire row register-resident (16 vals/thread), single gmem pass.
// Thread t owns elements [8t, 8t+8) and [2048+8t, 2048+8t+8).
// =====================================================================
__global__ void __launch_bounds__(256)
softmax_kernel(const __half* __restrict__ E, __nv_bfloat16* __restrict__ Aout)
{
    const size_t row = blockIdx.x;
    const uint4* e4 = (const uint4*)(E + row * NPIX);   // 8 halves per uint4
    const int t = threadIdx.x;
    const int lane = t & 31, warp = t >> 5;
    __shared__ float red[8];

    uint4 u[2];
    u[0] = e4[t];
    u[1] = e4[t + 256];

    float f[16];
#pragma unroll
    for (int i = 0; i < 2; i++) {
        const uint32_t* w = (const uint32_t*)&u[i];
#pragma unroll
        for (int j = 0; j < 4; j++) {
            float2 p = __half22float2(*(const __half2*)&w[j]);
            f[i * 8 + j * 2 + 0] = p.x;
            f[i * 8 + j * 2 + 1] = p.y;
        }
    }

    float mx = -3.0e38f;
#pragma unroll
    for (int i = 0; i < 16; i++) mx = fmaxf(mx, f[i]);
#pragma unroll
    for (int o = 16; o > 0; o >>= 1) mx = fmaxf(mx, __shfl_xor_sync(0xffffffffu, mx, o));
    if (lane == 0) red[warp] = mx;
    __syncthreads();
    float rmax = red[0];
#pragma unroll
    for (int i = 1; i < 8; i++) rmax = fmaxf(rmax, red[i]);
    __syncthreads();

    float s = 0.f;
#pragma unroll
    for (int i = 0; i < 16; i++) {
        f[i] = __expf(f[i] - rmax);
        s += f[i];
    }
#pragma unroll
    for (int o = 16; o > 0; o >>= 1) s += __shfl_xor_sync(0xffffffffu, s, o);
    if (lane == 0) red[warp] = s;
    __syncthreads();
    float rsum = 0.f;
#pragma unroll
    for (int i = 0; i < 8; i++) rsum += red[i];
    const float inv = 1.0f / rsum;

    uint4* a4 = (uint4*)(Aout + row * NPIX);            // 8 bf16 per uint4
#pragma unroll
    for (int i = 0; i < 2; i++) {
        uint32_t pk[4];
#pragma unroll
        for (int j = 0; j < 4; j++) {
            __nv_bfloat162 h = __floats2bfloat162_rn(f[i * 8 + j * 2 + 0] * inv,
                                                     f[i * 8 + j * 2 + 1] * inv);
            pk[j] = *(uint32_t*)&h;
        }
        a4[t + i * 256] = make_uint4(pk[0], pk[1], pk[2], pk[3]);
    }
}

// =====================================================================
// out[b][c][n] = gamma * O^T[b][n][c] + x[b][c][n]   (32x32 transpose)
// =====================================================================
__global__ void final_kernel(const float* __restrict__ O, const float* __restrict__ x,
                             const float* __restrict__ gamma, float* __restrict__ out)
{
    __shared__ float tile[32][33];
    const int b  = blockIdx.z;
    const int n0 = blockIdx.x * 32;
    const int c0 = blockIdx.y * 32;
    const int tx = threadIdx.x, ty = threadIdx.y;
    const float gm = gamma[0];
    const float* Ob = O + ((size_t)b * NPIX + n0) * CDIM + c0;
#pragma unroll
    for (int j = 0; j < 4; j++)
        tile[ty + 8 * j][tx] = Ob[(size_t)(ty + 8 * j) * CDIM + tx];   // tile[n][c]
    __syncthreads();
#pragma unroll
    for (int j = 0; j < 4; j++) {
        size_t idx = ((size_t)b * CDIM + c0 + ty + 8 * j) * NPIX + n0 + tx;
        out[idx] = gm * tile[tx][ty + 8 * j] + x[idx];
    }
}

// =====================================================================
// launch
// =====================================================================
extern "C" void kernel_launch(void* const* d_in, const int* in_sizes, int n_in,
                              void* d_out, int out_size)
{
    const float* x     = (const float*)d_in[0];
    const float* Wq    = (const float*)d_in[1];
    const float* bq    = (const float*)d_in[2];
    const float* Wk    = (const float*)d_in[3];
    const float* bk    = (const float*)d_in[4];
    const float* Wv    = (const float*)d_in[5];
    const float* bv    = (const float*)d_in[6];
    const float* gamma = (const float*)d_in[7];
    float* out = (float*)d_out;

    __nv_bfloat16 *Xs, *Ws, *Qs, *Ks, *Vt, *At;
    __half *Eh;
    float *O;
    cudaGetSymbolAddress((void**)&Xs, g_Xs);
    cudaGetSymbolAddress((void**)&Ws, g_Ws);
    cudaGetSymbolAddress((void**)&Qs, g_Qs);
    cudaGetSymbolAddress((void**)&Ks, g_Ks);
    cudaGetSymbolAddress((void**)&Vt, g_Vt);
    cudaGetSymbolAddress((void**)&At, g_At);
    cudaGetSymbolAddress((void**)&Eh, g_Eh);
    cudaGetSymbolAddress((void**)&O,  g_O);

    // opt-in dynamic smem (61,440 B/block; 2 blocks/SM = 122,880 B fits 228 KB)
    cudaFuncSetAttribute(gemm_kernel<__nv_bfloat16, 3, 128>,
                         cudaFuncAttributeMaxDynamicSharedMemorySize, SMEM_128);
    cudaFuncSetAttribute(gemm_kernel<__nv_bfloat16, 0, 128>,
                         cudaFuncAttributeMaxDynamicSharedMemorySize, SMEM_128);
    cudaFuncSetAttribute(gemm_kernel<__half, 0, 128>,
                         cudaFuncAttributeMaxDynamicSharedMemorySize, SMEM_128);
    cudaFuncSetAttribute(gemm_kernel<float, 0, 128>,
                         cudaFuncAttributeMaxDynamicSharedMemorySize, SMEM_128);

    // 1) converts into split layouts
    transpose_x_kernel<<<dim3(NPIX / 32, CDIM / 32, BATCH), dim3(32, 8)>>>(x, Xs);
    convert_w_kernel<<<dim3(256, 3), 256>>>(Wq, Wk, Wv, Ws);

    const size_t sNC  = (size_t)NPIX * CDIM;     // 4096*256
    const size_t sNN  = (size_t)NPIX * NPIX;     // 4096*4096
    const size_t s768 = (size_t)NPIX * KSPLIT;   // 4096*768

    // 2) fused QK proj: [Q|K] = Xs @ [Wsq;Wsk]^T : M=16384, N=512, K=768
    //    split outputs routed per-column to Qs (Q layout) / Ks (K layout)
    gemm_kernel<__nv_bfloat16, 3, 128><<<dim3(128, 4, 1), 256, SMEM_128>>>(
        Xs, KSPLIT, 0, Ws, KSPLIT, 0,
        Qs, KSPLIT, 0, KSPLIT, nullptr, bq, Ks, bk);

    // 3) Vt[b] = Wsv @ Xs[b]^T + bv(row) : M=256, N=4096, K=768, per batch
    gemm_kernel<__nv_bfloat16, 0, 128><<<dim3(2, 32, BATCH), 256, SMEM_128>>>(
        Ws + 2 * CDIM * KSPLIT, KSPLIT, 0, Xs, KSPLIT, s768,
        Vt, NPIX, sNC, KSPLIT, bv, nullptr, nullptr, nullptr);

    // 4) E[b] = Qs[b] @ Ks[b]^T : M=N=4096, K=768, fp16 out, 128x128 tile (2 CTA/SM)
    //    = Qh.Kh + Qh.Kl + Ql.Kh  (fp32-grade energies, fp16 storage)
    gemm_kernel<__half, 0, 128><<<dim3(32, 32, BATCH), 256, SMEM_128>>>(
        Qs, KSPLIT, s768, Ks, KSPLIT, s768,
        Eh, NPIX, sNN, KSPLIT, nullptr, nullptr, nullptr, nullptr);

    // 5) row softmax (fp16 in) -> attn bf16
    softmax_kernel<<<BATCH * NPIX, 256>>>(Eh, At);

    // 6) O^T[b] = attn[b] @ Vt[b]^T : M=4096, N=256, K=4096, fp32 out
    gemm_kernel<float, 0, 128><<<dim3(32, 2, BATCH), 256, SMEM_128>>>(
        At, NPIX, sNN, Vt, NPIX, sNC,
        O, CDIM, sNC, NPIX, nullptr, nullptr, nullptr, nullptr);

    // 7) out = gamma * O^T + x
    final_kernel<<<dim3(NPIX / 32, CDIM / 32, BATCH), dim3(32, 8)>>>(O, x, gamma, out);
}